// round 9
// baseline (speedup 1.0000x reference)
#include <cuda_runtime.h>
#include <cuda_bf16.h>
#include <math.h>

#define N_NODES 50000
#define N_EDGES 800000
#define E_TOT   (N_EDGES + N_NODES)   // edges + self loops = 850000
#define F       128                   // in/out feature dim
#define HEADS   4
#define HDIM    32
#define NEG_SLOPE 0.2f

// ----------------------------------------------------------------------------
// Scratch (device globals; no allocation allowed)
// ----------------------------------------------------------------------------
__device__ float g_x0[N_NODES * F];      // layer ping buffer
__device__ float g_x1[N_NODES * F];      // layer pong buffer
__device__ float g_h [N_NODES * F];      // h = x @ W (fp32)
__device__ float g_as[N_NODES * HEADS];  // alpha_src per node
__device__ float g_ad[N_NODES * HEADS];  // alpha_dst per node
__device__ int   g_deg[N_NODES];
__device__ int   g_off[N_NODES + 1];
__device__ int   g_cur[N_NODES];
__device__ int   g_csr[E_TOT];           // src node per CSR slot (grouped by dst)
__device__ int   g_dst[E_TOT];           // dst node per CSR slot
__device__ float g_q  [E_TOT * HEADS];   // edge weights exp(leaky(e)) per head

// ----------------------------------------------------------------------------
// Packed fp32x2 helpers (Blackwell: FFMA2 only reachable via PTX fma.rn.f32x2)
// ----------------------------------------------------------------------------
__device__ __forceinline__ unsigned long long pack2(float lo, float hi) {
    unsigned long long r;
    asm("mov.b64 %0, {%1, %2};" : "=l"(r) : "f"(lo), "f"(hi));
    return r;
}
__device__ __forceinline__ void unpack2(unsigned long long v, float& lo, float& hi) {
    asm("mov.b64 {%0, %1}, %2;" : "=f"(lo), "=f"(hi) : "l"(v));
}
#define FMA2(d, a, b) asm("fma.rn.f32x2 %0, %1, %2, %0;" : "+l"(d) : "l"(a), "l"(b))

// ----------------------------------------------------------------------------
// CSR construction (edge_index is int32)
// ----------------------------------------------------------------------------
__global__ void zero_deg_kernel(int* deg) {
    int i = blockIdx.x * blockDim.x + threadIdx.x;
    if (i < N_NODES) deg[i] = 0;
}

__global__ void hist_kernel(const int* __restrict__ ei, int* __restrict__ deg) {
    int i = blockIdx.x * blockDim.x + threadIdx.x;
    if (i >= E_TOT) return;
    int dst = (i < N_EDGES) ? ei[N_EDGES + i] : (i - N_EDGES);
    if (dst >= 0 && dst < N_NODES) atomicAdd(&deg[dst], 1);
}

// single-block exclusive scan over 50000 degrees
__global__ void scan_kernel(const int* __restrict__ deg, int* __restrict__ off,
                            int* __restrict__ cur) {
    __shared__ int part[1024];
    const int CH = (N_NODES + 1023) / 1024;  // 49
    int t = threadIdx.x;
    int b = t * CH;
    int e = min(b + CH, N_NODES);
    int s = 0;
    for (int i = b; i < e; i++) s += deg[i];
    part[t] = s;
    __syncthreads();
    for (int o = 1; o < 1024; o <<= 1) {
        int v = (t >= o) ? part[t - o] : 0;
        __syncthreads();
        part[t] += v;
        __syncthreads();
    }
    int run = (t == 0) ? 0 : part[t - 1];
    for (int i = b; i < e; i++) {
        off[i] = run;
        cur[i] = run;
        run += deg[i];
    }
    if (t == 0) off[N_NODES] = part[1023];
}

__global__ void fill_kernel(const int* __restrict__ ei, int* __restrict__ cur,
                            int* __restrict__ csr, int* __restrict__ dstv) {
    int i = blockIdx.x * blockDim.x + threadIdx.x;
    if (i >= E_TOT) return;
    int src, dst;
    if (i < N_EDGES) { src = ei[i]; dst = ei[N_EDGES + i]; }
    else             { src = i - N_EDGES; dst = src; }
    if (dst < 0 || dst >= N_NODES) return;
    if (src < 0) src = 0; if (src >= N_NODES) src = N_NODES - 1;
    int pos = atomicAdd(&cur[dst], 1);
    csr[pos] = src;
    dstv[pos] = dst;
}

// ----------------------------------------------------------------------------
// GEMM + alpha fusion: h[N,128] = x[N,128] @ W[128,128] (fp32),
// as[n,head] = <h[n,head,:], a_s[head,:]> via 8-lane butterfly.
// 64-row tile, 256 threads. Inner product uses packed fma.rn.f32x2.
// ----------------------------------------------------------------------------
__global__ __launch_bounds__(256) void gemm_alpha_kernel(
    const float* __restrict__ x, const float* __restrict__ W,
    const float* __restrict__ a_s, const float* __restrict__ a_d,
    float* __restrict__ h, float* __restrict__ out_s, float* __restrict__ out_d) {
    __shared__ float xs[64 * F];
    int t = threadIdx.x;
    int row0 = blockIdx.x * 64;

    const float4* x4 = reinterpret_cast<const float4*>(x);
    float4* xs4 = reinterpret_cast<float4*>(xs);
#pragma unroll
    for (int i = 0; i < 8; i++) {
        int idx = t + i * 256;          // 0..2047 float4 slots
        int r = idx >> 5;
        int cc = idx & 31;
        float4 v = make_float4(0.f, 0.f, 0.f, 0.f);
        if (row0 + r < N_NODES) v = x4[(size_t)(row0 + r) * 32 + cc];
        xs4[idx] = v;
    }
    __syncthreads();

    int t_row = t >> 5, t_col = t & 31;

    unsigned long long acc2[4][4];  // [row-pair][col j]
#pragma unroll
    for (int rr = 0; rr < 4; rr++)
#pragma unroll
        for (int j = 0; j < 4; j++) acc2[rr][j] = pack2(0.f, 0.f);

    const float4* W4 = reinterpret_cast<const float4*>(W);
    const float* xbase = xs + t_row * 8 * F;
#pragma unroll 4
    for (int k = 0; k < F; k++) {
        float4 w = W4[k * 32 + t_col];
        unsigned long long w0 = pack2(w.x, w.x);
        unsigned long long w1 = pack2(w.y, w.y);
        unsigned long long w2 = pack2(w.z, w.z);
        unsigned long long w3 = pack2(w.w, w.w);
#pragma unroll
        for (int rr = 0; rr < 4; rr++) {
            float xa = xbase[(2 * rr) * F + k];
            float xb = xbase[(2 * rr + 1) * F + k];
            unsigned long long xp = pack2(xa, xb);
            FMA2(acc2[rr][0], xp, w0);
            FMA2(acc2[rr][1], xp, w1);
            FMA2(acc2[rr][2], xp, w2);
            FMA2(acc2[rr][3], xp, w3);
        }
    }

    float accf[8][4];
#pragma unroll
    for (int rr = 0; rr < 4; rr++)
#pragma unroll
        for (int j = 0; j < 4; j++)
            unpack2(acc2[rr][j], accf[2 * rr][j], accf[2 * rr + 1][j]);

    // store h (fp32)
    float4* h4 = reinterpret_cast<float4*>(h);
#pragma unroll
    for (int r = 0; r < 8; r++) {
        int row = row0 + t_row * 8 + r;
        if (row < N_NODES)
            h4[(size_t)row * 32 + t_col] =
                make_float4(accf[r][0], accf[r][1], accf[r][2], accf[r][3]);
    }

    // fused alpha: channels of head hd live in lanes t_col = 8*hd..8*hd+7
    float4 asv = reinterpret_cast<const float4*>(a_s)[t_col];
    float4 adv = reinterpret_cast<const float4*>(a_d)[t_col];
    int head = t_col >> 3;
#pragma unroll
    for (int r = 0; r < 8; r++) {
        int row = row0 + t_row * 8 + r;
        float ps = accf[r][0] * asv.x + accf[r][1] * asv.y +
                   accf[r][2] * asv.z + accf[r][3] * asv.w;
        float pd = accf[r][0] * adv.x + accf[r][1] * adv.y +
                   accf[r][2] * adv.z + accf[r][3] * adv.w;
#pragma unroll
        for (int o = 1; o < 8; o <<= 1) {
            ps += __shfl_xor_sync(0xffffffffu, ps, o);
            pd += __shfl_xor_sync(0xffffffffu, pd, o);
        }
        if ((t_col & 7) == 0 && row < N_NODES) {
            out_s[row * HEADS + head] = ps;
            out_d[row * HEADS + head] = pd;
        }
    }
}

// ----------------------------------------------------------------------------
// Edge weights, edge-parallel: q4[pos] = exp(leaky(as4[src] + ad4[dst])).
// Coalesced pos-indexed I/O; removes the as-gather + exp from agg's hot loop.
// (No segment-max: softmax is shift-invariant; logits O(10) << exp overflow.)
// ----------------------------------------------------------------------------
__global__ __launch_bounds__(256) void edge_q_kernel(
    const int* __restrict__ csr, const int* __restrict__ dstv,
    const float* __restrict__ as, const float* __restrict__ ad,
    float* __restrict__ q) {
    int pos = blockIdx.x * blockDim.x + threadIdx.x;
    if (pos >= E_TOT) return;
    int src = csr[pos];
    int dst = dstv[pos];
    float4 av = reinterpret_cast<const float4*>(as)[src];
    float4 dv = reinterpret_cast<const float4*>(ad)[dst];
    float e0 = av.x + dv.x; e0 = e0 > 0.f ? e0 : NEG_SLOPE * e0;
    float e1 = av.y + dv.y; e1 = e1 > 0.f ? e1 : NEG_SLOPE * e1;
    float e2 = av.z + dv.z; e2 = e2 > 0.f ? e2 : NEG_SLOPE * e2;
    float e3 = av.w + dv.w; e3 = e3 > 0.f ? e3 : NEG_SLOPE * e3;
    float4 qv;
    qv.x = __expf(e0); qv.y = __expf(e1);
    qv.z = __expf(e2); qv.w = __expf(e3);
    reinterpret_cast<float4*>(q)[pos] = qv;
}

// ----------------------------------------------------------------------------
// Aggregation: one warp per dst node. Per edge: csr int (coalesced),
// q scalar (pos-indexed -> independent of csr chain), h LDG.128, 4 FFMA.
// Unroll x8 for deep MLP. den identical across the 8 lanes of a head.
// out[n,c] = relu(acc/den + bias[c]).
// ----------------------------------------------------------------------------
__global__ __launch_bounds__(256) void agg_kernel(
    const float* __restrict__ h, const int* __restrict__ off,
    const int* __restrict__ csr, const float* __restrict__ q,
    const float* __restrict__ bias, float* __restrict__ out) {
    int warp = threadIdx.x >> 5;
    int lane = threadIdx.x & 31;
    int n = blockIdx.x * 8 + warp;
    if (n >= N_NODES) return;

    int head = lane >> 3;
    const float4* h4 = reinterpret_cast<const float4*>(h);
    const float* qh = q + head;

    float4 acc = make_float4(0.f, 0.f, 0.f, 0.f);
    float den = 0.f;
    int s0 = off[n], s1 = off[n + 1];

    int pos = s0;
    for (; pos + 8 <= s1; pos += 8) {
        int i0 = csr[pos];     int i1 = csr[pos + 1];
        int i2 = csr[pos + 2]; int i3 = csr[pos + 3];
        int i4 = csr[pos + 4]; int i5 = csr[pos + 5];
        int i6 = csr[pos + 6]; int i7 = csr[pos + 7];
        float q0 = __ldg(&qh[(size_t)(pos) * 4]);
        float q1 = __ldg(&qh[(size_t)(pos + 1) * 4]);
        float q2 = __ldg(&qh[(size_t)(pos + 2) * 4]);
        float q3 = __ldg(&qh[(size_t)(pos + 3) * 4]);
        float q4v = __ldg(&qh[(size_t)(pos + 4) * 4]);
        float q5 = __ldg(&qh[(size_t)(pos + 5) * 4]);
        float q6 = __ldg(&qh[(size_t)(pos + 6) * 4]);
        float q7 = __ldg(&qh[(size_t)(pos + 7) * 4]);
        float4 h0 = h4[(size_t)i0 * 32 + lane];
        float4 h1 = h4[(size_t)i1 * 32 + lane];
        float4 h2 = h4[(size_t)i2 * 32 + lane];
        float4 h3 = h4[(size_t)i3 * 32 + lane];
        float4 h5v = h4[(size_t)i4 * 32 + lane];
        float4 h6v = h4[(size_t)i5 * 32 + lane];
        float4 h7v = h4[(size_t)i6 * 32 + lane];
        float4 h8v = h4[(size_t)i7 * 32 + lane];
        acc.x += q0 * h0.x + q1 * h1.x + q2 * h2.x + q3 * h3.x;
        acc.y += q0 * h0.y + q1 * h1.y + q2 * h2.y + q3 * h3.y;
        acc.z += q0 * h0.z + q1 * h1.z + q2 * h2.z + q3 * h3.z;
        acc.w += q0 * h0.w + q1 * h1.w + q2 * h2.w + q3 * h3.w;
        acc.x += q4v * h5v.x + q5 * h6v.x + q6 * h7v.x + q7 * h8v.x;
        acc.y += q4v * h5v.y + q5 * h6v.y + q6 * h7v.y + q7 * h8v.y;
        acc.z += q4v * h5v.z + q5 * h6v.z + q6 * h7v.z + q7 * h8v.z;
        acc.w += q4v * h5v.w + q5 * h6v.w + q6 * h7v.w + q7 * h8v.w;
        den += ((q0 + q1) + (q2 + q3)) + ((q4v + q5) + (q6 + q7));
    }
    for (; pos < s1; pos++) {
        int i0 = csr[pos];
        float q0 = __ldg(&qh[(size_t)pos * 4]);
        float4 h0 = h4[(size_t)i0 * 32 + lane];
        acc.x += q0 * h0.x; acc.y += q0 * h0.y;
        acc.z += q0 * h0.z; acc.w += q0 * h0.w;
        den += q0;
    }

    float inv = 1.f / den;   // deg >= 1 (self loop), den > 0
    float4 bv = reinterpret_cast<const float4*>(bias)[lane];
    float4 o;
    o.x = fmaxf(acc.x * inv + bv.x, 0.f);
    o.y = fmaxf(acc.y * inv + bv.y, 0.f);
    o.z = fmaxf(acc.z * inv + bv.z, 0.f);
    o.w = fmaxf(acc.w * inv + bv.w, 0.f);
    reinterpret_cast<float4*>(out)[(size_t)n * 32 + lane] = o;
}

// ----------------------------------------------------------------------------
// Launch
// ----------------------------------------------------------------------------
extern "C" void kernel_launch(void* const* d_in, const int* in_sizes, int n_in,
                              void* d_out, int out_size) {
    const float* x    = (const float*)d_in[0];
    const int*   ei   = (const int*)d_in[1];
    const float* Ws   = (const float*)d_in[2];
    const float* a_s  = (const float*)d_in[3];
    const float* a_d  = (const float*)d_in[4];
    const float* bias = (const float*)d_in[5];
    float*       out  = (float*)d_out;

    void* pv;
    cudaGetSymbolAddress(&pv, g_x0);  float* x0  = (float*)pv;
    cudaGetSymbolAddress(&pv, g_x1);  float* x1  = (float*)pv;
    cudaGetSymbolAddress(&pv, g_h);   float* h   = (float*)pv;
    cudaGetSymbolAddress(&pv, g_as);  float* as  = (float*)pv;
    cudaGetSymbolAddress(&pv, g_ad);  float* ad  = (float*)pv;
    cudaGetSymbolAddress(&pv, g_deg); int*   deg = (int*)pv;
    cudaGetSymbolAddress(&pv, g_off); int*   off = (int*)pv;
    cudaGetSymbolAddress(&pv, g_cur); int*   cur = (int*)pv;
    cudaGetSymbolAddress(&pv, g_csr); int*   csr = (int*)pv;
    cudaGetSymbolAddress(&pv, g_dst); int*   dstv= (int*)pv;
    cudaGetSymbolAddress(&pv, g_q);   float* q   = (float*)pv;

    // CSR build (once; reused by all 3 layers)
    zero_deg_kernel<<<(N_NODES + 255) / 256, 256>>>(deg);
    hist_kernel<<<(E_TOT + 255) / 256, 256>>>(ei, deg);
    scan_kernel<<<1, 1024>>>(deg, off, cur);
    fill_kernel<<<(E_TOT + 255) / 256, 256>>>(ei, cur, csr, dstv);

    for (int l = 0; l < 3; l++) {
        const float* xin = (l == 0) ? x : ((l == 1) ? x0 : x1);
        float* xout = (l == 0) ? x0 : ((l == 1) ? x1 : out);
        gemm_alpha_kernel<<<(N_NODES + 63) / 64, 256>>>(
            xin, Ws + (size_t)l * F * F, a_s + l * F, a_d + l * F, h, as, ad);
        edge_q_kernel<<<(E_TOT + 255) / 256, 256>>>(csr, dstv, as, ad, q);
        agg_kernel<<<(N_NODES + 7) / 8, 256>>>(h, off, csr, q, bias + l * F, xout);
    }
}

// round 10
// speedup vs baseline: 1.5000x; 1.5000x over previous
#include <cuda_runtime.h>
#include <cuda_bf16.h>
#include <math.h>

#define N_NODES 50000
#define N_EDGES 800000
#define E_TOT   (N_EDGES + N_NODES)   // edges + self loops = 850000
#define F       128                   // in/out feature dim
#define HEADS   4
#define HDIM    32
#define NEG_SLOPE 0.2f

// GEMM smem layout (tf32 staging, padded for conflict-free fragment LDS)
#define XS_STRIDE 132                 // 64 x 132 uint  (33792 B)
#define WS_STRIDE 136                 // 128 x 136 uint (69632 B)
#define GEMM_SMEM (64 * XS_STRIDE * 4 + 128 * WS_STRIDE * 4)   // 103424 B

// ----------------------------------------------------------------------------
// Scratch (device globals; no allocation allowed)
// ----------------------------------------------------------------------------
__device__ float g_x0[N_NODES * F];      // layer ping buffer
__device__ float g_x1[N_NODES * F];      // layer pong buffer
__device__ float g_h [N_NODES * F];      // h = x @ W (fp32)
__device__ float g_as[N_NODES * HEADS];  // alpha_src per node
__device__ float g_ad[N_NODES * HEADS];  // alpha_dst per node
__device__ int   g_deg[N_NODES];
__device__ int   g_off[N_NODES + 1];
__device__ int   g_cur[N_NODES];
__device__ int   g_csr[E_TOT];           // src node per CSR slot (grouped by dst)

// ----------------------------------------------------------------------------
// tf32 / mma helpers
// ----------------------------------------------------------------------------
__device__ __forceinline__ unsigned int f2tf32(float f) {
    unsigned int u;
    asm("cvt.rna.tf32.f32 %0, %1;" : "=r"(u) : "f"(f));
    return u;
}
__device__ __forceinline__ void mma_tf32(float* c,
    unsigned int a0, unsigned int a1, unsigned int a2, unsigned int a3,
    unsigned int b0, unsigned int b1) {
    asm("mma.sync.aligned.m16n8k8.row.col.f32.tf32.tf32.f32 "
        "{%0,%1,%2,%3}, {%4,%5,%6,%7}, {%8,%9}, {%0,%1,%2,%3};"
        : "+f"(c[0]), "+f"(c[1]), "+f"(c[2]), "+f"(c[3])
        : "r"(a0), "r"(a1), "r"(a2), "r"(a3), "r"(b0), "r"(b1));
}

// ----------------------------------------------------------------------------
// CSR construction (edge_index is int32)
// ----------------------------------------------------------------------------
__global__ void zero_deg_kernel(int* deg) {
    int i = blockIdx.x * blockDim.x + threadIdx.x;
    if (i < N_NODES) deg[i] = 0;
}

__global__ void hist_kernel(const int* __restrict__ ei, int* __restrict__ deg) {
    int i = blockIdx.x * blockDim.x + threadIdx.x;
    if (i >= E_TOT) return;
    int dst = (i < N_EDGES) ? ei[N_EDGES + i] : (i - N_EDGES);
    if (dst >= 0 && dst < N_NODES) atomicAdd(&deg[dst], 1);
}

// single-block exclusive scan over 50000 degrees
__global__ void scan_kernel(const int* __restrict__ deg, int* __restrict__ off,
                            int* __restrict__ cur) {
    __shared__ int part[1024];
    const int CH = (N_NODES + 1023) / 1024;  // 49
    int t = threadIdx.x;
    int b = t * CH;
    int e = min(b + CH, N_NODES);
    int s = 0;
    for (int i = b; i < e; i++) s += deg[i];
    part[t] = s;
    __syncthreads();
    for (int o = 1; o < 1024; o <<= 1) {
        int v = (t >= o) ? part[t - o] : 0;
        __syncthreads();
        part[t] += v;
        __syncthreads();
    }
    int run = (t == 0) ? 0 : part[t - 1];
    for (int i = b; i < e; i++) {
        off[i] = run;
        cur[i] = run;
        run += deg[i];
    }
    if (t == 0) off[N_NODES] = part[1023];
}

__global__ void fill_kernel(const int* __restrict__ ei, int* __restrict__ cur,
                            int* __restrict__ csr) {
    int i = blockIdx.x * blockDim.x + threadIdx.x;
    if (i >= E_TOT) return;
    int src, dst;
    if (i < N_EDGES) { src = ei[i]; dst = ei[N_EDGES + i]; }
    else             { src = i - N_EDGES; dst = src; }
    if (dst < 0 || dst >= N_NODES) return;
    if (src < 0) src = 0; if (src >= N_NODES) src = N_NODES - 1;
    int pos = atomicAdd(&cur[dst], 1);
    csr[pos] = src;
}

// ----------------------------------------------------------------------------
// tf32 tensor-core GEMM + alpha fusion.
// Tile 64x128 per 256-thread block; warp w owns rows (w%4)*16, cols (w/4)*64.
// X, W staged to smem as tf32 (cvt.rna) with padded strides (bank-clean frags).
// Epilogue: C frags -> smem -> fused fp32 h-store + alpha dot + 8-lane butterfly.
// ----------------------------------------------------------------------------
__global__ __launch_bounds__(256) void gemm_tf32_alpha_kernel(
    const float* __restrict__ x, const float* __restrict__ W,
    const float* __restrict__ a_s, const float* __restrict__ a_d,
    float* __restrict__ h, float* __restrict__ out_s, float* __restrict__ out_d) {
    extern __shared__ unsigned int smem_u[];
    unsigned int* Xs = smem_u;                       // 64 x XS_STRIDE
    unsigned int* Wsm = smem_u + 64 * XS_STRIDE;     // 128 x WS_STRIDE
    int t = threadIdx.x;
    int row0 = blockIdx.x * 64;

    // stage X tile (tf32)
    const float4* x4 = reinterpret_cast<const float4*>(x);
#pragma unroll
    for (int i = 0; i < 8; i++) {
        int idx = t + i * 256;          // 2048 float4 slots (64 rows x 32)
        int r = idx >> 5, c4 = idx & 31;
        float4 v = make_float4(0.f, 0.f, 0.f, 0.f);
        if (row0 + r < N_NODES) v = x4[(size_t)(row0 + r) * 32 + c4];
        uint4 u = make_uint4(f2tf32(v.x), f2tf32(v.y), f2tf32(v.z), f2tf32(v.w));
        *reinterpret_cast<uint4*>(Xs + r * XS_STRIDE + c4 * 4) = u;
    }
    // stage W (tf32)
    const float4* W4 = reinterpret_cast<const float4*>(W);
#pragma unroll
    for (int i = 0; i < 16; i++) {
        int idx = t + i * 256;          // 4096 float4 slots (128 rows x 32)
        int r = idx >> 5, c4 = idx & 31;
        float4 v = W4[r * 32 + c4];
        uint4 u = make_uint4(f2tf32(v.x), f2tf32(v.y), f2tf32(v.z), f2tf32(v.w));
        *reinterpret_cast<uint4*>(Wsm + r * WS_STRIDE + c4 * 4) = u;
    }
    __syncthreads();

    int warp = t >> 5, lane = t & 31;
    int gid = lane >> 2, tid4 = lane & 3;
    int r0 = (warp & 3) * 16;
    int j0 = (warp >> 2) * 64;

    float c[8][4];
#pragma unroll
    for (int nt = 0; nt < 8; nt++)
#pragma unroll
        for (int j = 0; j < 4; j++) c[nt][j] = 0.f;

#pragma unroll 2
    for (int k0 = 0; k0 < F; k0 += 8) {
        unsigned int a0 = Xs[(r0 + gid) * XS_STRIDE + k0 + tid4];
        unsigned int a1 = Xs[(r0 + gid + 8) * XS_STRIDE + k0 + tid4];
        unsigned int a2 = Xs[(r0 + gid) * XS_STRIDE + k0 + 4 + tid4];
        unsigned int a3 = Xs[(r0 + gid + 8) * XS_STRIDE + k0 + 4 + tid4];
#pragma unroll
        for (int nt = 0; nt < 8; nt++) {
            int jb = j0 + nt * 8;
            unsigned int b0 = Wsm[(k0 + tid4) * WS_STRIDE + jb + gid];
            unsigned int b1 = Wsm[(k0 + tid4 + 4) * WS_STRIDE + jb + gid];
            mma_tf32(c[nt], a0, a1, a2, a3, b0, b1);
        }
    }
    __syncthreads();

    // C frags -> smem (reuse Xs region as float hs[64][XS_STRIDE])
    float* hs = reinterpret_cast<float*>(smem_u);
#pragma unroll
    for (int nt = 0; nt < 8; nt++) {
        int jb = j0 + nt * 8 + tid4 * 2;
        *reinterpret_cast<float2*>(hs + (r0 + gid) * XS_STRIDE + jb) =
            make_float2(c[nt][0], c[nt][1]);
        *reinterpret_cast<float2*>(hs + (r0 + gid + 8) * XS_STRIDE + jb) =
            make_float2(c[nt][2], c[nt][3]);
    }
    __syncthreads();

    // fused h store + alpha: thread (t_row, t_col) handles rows t_row*8..+8,
    // channels t_col*4..+4; head = t_col>>3, butterfly over 8 lanes.
    int t_row = t >> 5, t_col = t & 31;
    float4 asv = reinterpret_cast<const float4*>(a_s)[t_col];
    float4 adv = reinterpret_cast<const float4*>(a_d)[t_col];
    int head = t_col >> 3;
    float4* h4 = reinterpret_cast<float4*>(h);
#pragma unroll
    for (int r = 0; r < 8; r++) {
        int row = row0 + t_row * 8 + r;
        float4 hv = *reinterpret_cast<float4*>(hs + (t_row * 8 + r) * XS_STRIDE + t_col * 4);
        if (row < N_NODES)
            h4[(size_t)row * 32 + t_col] = hv;
        float ps = hv.x * asv.x + hv.y * asv.y + hv.z * asv.z + hv.w * asv.w;
        float pd = hv.x * adv.x + hv.y * adv.y + hv.z * adv.z + hv.w * adv.w;
#pragma unroll
        for (int o = 1; o < 8; o <<= 1) {
            ps += __shfl_xor_sync(0xffffffffu, ps, o);
            pd += __shfl_xor_sync(0xffffffffu, pd, o);
        }
        if ((t_col & 7) == 0 && row < N_NODES) {
            out_s[row * HEADS + head] = ps;
            out_d[row * HEADS + head] = pd;
        }
    }
}

// ----------------------------------------------------------------------------
// Fused softmax + aggregation (R4 reference version): one warp per dst node.
// lane covers channels 4*lane..4*lane+3; head = lane>>3.
// q identical across the 8 lanes of a head -> den needs no reduction.
// ----------------------------------------------------------------------------
__global__ __launch_bounds__(256) void agg_fused_kernel(
    const float* __restrict__ h, const int* __restrict__ off,
    const int* __restrict__ csr, const float* __restrict__ as,
    const float* __restrict__ ad, const float* __restrict__ bias,
    float* __restrict__ out) {
    int warp = threadIdx.x >> 5;
    int lane = threadIdx.x & 31;
    int n = blockIdx.x * 8 + warp;
    if (n >= N_NODES) return;

    int head = lane >> 3;
    float ad_h = ad[n * HEADS + head];
    const float4* h4 = reinterpret_cast<const float4*>(h);

    float4 acc = make_float4(0.f, 0.f, 0.f, 0.f);
    float den = 0.f;
    int s0 = off[n], s1 = off[n + 1];

    int pos = s0;
    for (; pos + 4 <= s1; pos += 4) {
        int sa = csr[pos];
        int sb = csr[pos + 1];
        int sc = csr[pos + 2];
        int sd = csr[pos + 3];
        float ea = as[sa * HEADS + head] + ad_h;
        float eb = as[sb * HEADS + head] + ad_h;
        float ec = as[sc * HEADS + head] + ad_h;
        float ed = as[sd * HEADS + head] + ad_h;
        ea = ea > 0.f ? ea : NEG_SLOPE * ea;
        eb = eb > 0.f ? eb : NEG_SLOPE * eb;
        ec = ec > 0.f ? ec : NEG_SLOPE * ec;
        ed = ed > 0.f ? ed : NEG_SLOPE * ed;
        float qa = __expf(ea), qb = __expf(eb), qc = __expf(ec), qd = __expf(ed);
        float4 ha = h4[(size_t)sa * 32 + lane];
        float4 hb = h4[(size_t)sb * 32 + lane];
        float4 hc = h4[(size_t)sc * 32 + lane];
        float4 hd = h4[(size_t)sd * 32 + lane];
        acc.x += qa * ha.x + qb * hb.x + qc * hc.x + qd * hd.x;
        acc.y += qa * ha.y + qb * hb.y + qc * hc.y + qd * hd.y;
        acc.z += qa * ha.z + qb * hb.z + qc * hc.z + qd * hd.z;
        acc.w += qa * ha.w + qb * hb.w + qc * hc.w + qd * hd.w;
        den += (qa + qb) + (qc + qd);
    }
    for (; pos < s1; pos++) {
        int sa = csr[pos];
        float e = as[sa * HEADS + head] + ad_h;
        e = e > 0.f ? e : NEG_SLOPE * e;
        float q = __expf(e);
        float4 ha = h4[(size_t)sa * 32 + lane];
        acc.x += q * ha.x; acc.y += q * ha.y;
        acc.z += q * ha.z; acc.w += q * ha.w;
        den += q;
    }

    float inv = 1.f / den;   // deg >= 1 (self loop), den > 0
    float4 bv = reinterpret_cast<const float4*>(bias)[lane];
    float4 o;
    o.x = fmaxf(acc.x * inv + bv.x, 0.f);
    o.y = fmaxf(acc.y * inv + bv.y, 0.f);
    o.z = fmaxf(acc.z * inv + bv.z, 0.f);
    o.w = fmaxf(acc.w * inv + bv.w, 0.f);
    reinterpret_cast<float4*>(out)[(size_t)n * 32 + lane] = o;
}

// ----------------------------------------------------------------------------
// Launch
// ----------------------------------------------------------------------------
extern "C" void kernel_launch(void* const* d_in, const int* in_sizes, int n_in,
                              void* d_out, int out_size) {
    const float* x    = (const float*)d_in[0];
    const int*   ei   = (const int*)d_in[1];
    const float* Ws   = (const float*)d_in[2];
    const float* a_s  = (const float*)d_in[3];
    const float* a_d  = (const float*)d_in[4];
    const float* bias = (const float*)d_in[5];
    float*       out  = (float*)d_out;

    void* pv;
    cudaGetSymbolAddress(&pv, g_x0);  float* x0  = (float*)pv;
    cudaGetSymbolAddress(&pv, g_x1);  float* x1  = (float*)pv;
    cudaGetSymbolAddress(&pv, g_h);   float* h   = (float*)pv;
    cudaGetSymbolAddress(&pv, g_as);  float* as  = (float*)pv;
    cudaGetSymbolAddress(&pv, g_ad);  float* ad  = (float*)pv;
    cudaGetSymbolAddress(&pv, g_deg); int*   deg = (int*)pv;
    cudaGetSymbolAddress(&pv, g_off); int*   off = (int*)pv;
    cudaGetSymbolAddress(&pv, g_cur); int*   cur = (int*)pv;
    cudaGetSymbolAddress(&pv, g_csr); int*   csr = (int*)pv;

    cudaFuncSetAttribute(gemm_tf32_alpha_kernel,
                         cudaFuncAttributeMaxDynamicSharedMemorySize, GEMM_SMEM);

    // CSR build (once; reused by all 3 layers)
    zero_deg_kernel<<<(N_NODES + 255) / 256, 256>>>(deg);
    hist_kernel<<<(E_TOT + 255) / 256, 256>>>(ei, deg);
    scan_kernel<<<1, 1024>>>(deg, off, cur);
    fill_kernel<<<(E_TOT + 255) / 256, 256>>>(ei, cur, csr);

    for (int l = 0; l < 3; l++) {
        const float* xin = (l == 0) ? x : ((l == 1) ? x0 : x1);
        float* xout = (l == 0) ? x0 : ((l == 1) ? x1 : out);
        gemm_tf32_alpha_kernel<<<(N_NODES + 63) / 64, 256, GEMM_SMEM>>>(
            xin, Ws + (size_t)l * F * F, a_s + l * F, a_d + l * F, h, as, ad);
        agg_fused_kernel<<<(N_NODES + 7) / 8, 256>>>(
            h, off, csr, as, ad, bias + l * F, xout);
    }
}